// round 1
// baseline (speedup 1.0000x reference)
#include <cuda_runtime.h>
#include <cuda_bf16.h>
#include <math.h>

// ---------------------------------------------------------------------------
// Scratch (ping-pong). Max tensor: conv0 out = 64*64*64*64 = 16.78M floats.
// ---------------------------------------------------------------------------
__device__ float g_A[64 * 64 * 64 * 64];   // 67.1 MB
__device__ float g_B[64 * 128 * 32 * 32];  // 33.6 MB

// ---------------------------------------------------------------------------
// Direct conv3x3 SAME + bias + ReLU.
// Layout: in [B,CI,H,W], wt [CO,CI,3,3], out [B,CO,H,W].
// Block: handles one image, OCT output channels, TPHxTPW spatial tile.
// Thread: RC channels x RPH x RPW pixels.
// ---------------------------------------------------------------------------
template <int H, int W, int CI, int CO,
          int TPH, int TPW, int RPH, int RPW,
          int OCT, int RC, int ICT>
__global__ void __launch_bounds__((TPH / RPH) * (TPW / RPW) * (OCT / RC))
conv3x3_relu(const float* __restrict__ in, const float* __restrict__ wt,
             const float* __restrict__ bias, float* __restrict__ out)
{
    constexpr int NPX_H = TPH / RPH;
    constexpr int NPX_W = TPW / RPW;
    constexpr int NPX = NPX_H * NPX_W;
    constexpr int NCH = OCT / RC;
    constexpr int NT = NPX * NCH;

    const int b   = blockIdx.z;
    const int oc0 = blockIdx.y * OCT;
    const int tiles_w = W / TPW;
    const int ty0 = (blockIdx.x / tiles_w) * TPH;
    const int tx0 = (blockIdx.x % tiles_w) * TPW;

    const int tid    = threadIdx.x;
    const int pix_id = tid % NPX;
    const int ch_id  = tid / NPX;
    const int ly = (pix_id / NPX_W) * RPH;   // local pixel y within tile
    const int lx = (pix_id % NPX_W) * RPW;
    const int py = ty0 + ly;
    const int px = tx0 + lx;
    const int oc = oc0 + ch_id * RC;

    __shared__ float s_in[ICT][TPH + 2][TPW + 2];
    __shared__ float s_w[ICT][OCT][9];

    float acc[RC][RPH][RPW];
#pragma unroll
    for (int c = 0; c < RC; c++)
#pragma unroll
        for (int yy = 0; yy < RPH; yy++)
#pragma unroll
            for (int xx = 0; xx < RPW; xx++) acc[c][yy][xx] = 0.f;

    for (int ic0 = 0; ic0 < CI; ic0 += ICT) {
        __syncthreads();
        // load input tile with halo
        constexpr int IN_ELEMS = ICT * (TPH + 2) * (TPW + 2);
        for (int idx = tid; idx < IN_ELEMS; idx += NT) {
            int ic  = idx / ((TPH + 2) * (TPW + 2));
            int rem = idx % ((TPH + 2) * (TPW + 2));
            int iy = rem / (TPW + 2), ix = rem % (TPW + 2);
            int gy = ty0 + iy - 1, gx = tx0 + ix - 1;
            float v = 0.f;
            if (gy >= 0 && gy < H && gx >= 0 && gx < W)
                v = in[((size_t)(b * CI + ic0 + ic) * H + gy) * W + gx];
            s_in[ic][iy][ix] = v;
        }
        // load weights slice
        constexpr int W_ELEMS = ICT * OCT * 9;
        for (int idx = tid; idx < W_ELEMS; idx += NT) {
            int ic  = idx / (OCT * 9);
            int rem = idx % (OCT * 9);
            int o = rem / 9, t = rem % 9;
            s_w[ic][o][t] = wt[((size_t)(oc0 + o) * CI + ic0 + ic) * 9 + t];
        }
        __syncthreads();

#pragma unroll
        for (int ic = 0; ic < ICT; ic++) {
            float r_in[RPH + 2][RPW + 2];
#pragma unroll
            for (int yy = 0; yy < RPH + 2; yy++)
#pragma unroll
                for (int xx = 0; xx < RPW + 2; xx++)
                    r_in[yy][xx] = s_in[ic][ly + yy][lx + xx];
#pragma unroll
            for (int c = 0; c < RC; c++) {
                float w[9];
#pragma unroll
                for (int t = 0; t < 9; t++) w[t] = s_w[ic][ch_id * RC + c][t];
#pragma unroll
                for (int yy = 0; yy < RPH; yy++)
#pragma unroll
                    for (int xx = 0; xx < RPW; xx++) {
                        float a = acc[c][yy][xx];
#pragma unroll
                        for (int ky = 0; ky < 3; ky++)
#pragma unroll
                            for (int kx = 0; kx < 3; kx++)
                                a = fmaf(w[ky * 3 + kx], r_in[yy + ky][xx + kx], a);
                        acc[c][yy][xx] = a;
                    }
            }
        }
    }

#pragma unroll
    for (int c = 0; c < RC; c++) {
        float bv = bias[oc + c];
#pragma unroll
        for (int yy = 0; yy < RPH; yy++)
#pragma unroll
            for (int xx = 0; xx < RPW; xx++) {
                float v = acc[c][yy][xx] + bv;
                out[((size_t)(b * CO + oc + c) * H + py + yy) * W + px + xx] =
                    fmaxf(v, 0.f);
            }
    }
}

// ---------------------------------------------------------------------------
// 2x2 max pool, stride 2.
// ---------------------------------------------------------------------------
__global__ void maxpool2k(const float* __restrict__ in, float* __restrict__ out,
                          int total, int C, int H, int W)
{
    int i = blockIdx.x * blockDim.x + threadIdx.x;
    if (i >= total) return;
    int WO = W >> 1, HO = H >> 1;
    int x = i % WO;
    int t = i / WO;
    int y = t % HO; t /= HO;
    int c = t % C;
    int b = t / C;
    const float* p = in + ((size_t)(b * C + c) * H + 2 * y) * W + 2 * x;
    out[i] = fmaxf(fmaxf(p[0], p[1]), fmaxf(p[W], p[W + 1]));
}

// ---------------------------------------------------------------------------
// Engram mask + final 2x2 pool (4x4 -> 2x2) + flatten to [B, 2048].
// One block per image, 512 threads (one per channel).
// ---------------------------------------------------------------------------
__global__ void mask_pool_flatten(const float* __restrict__ h,
                                  const int* __restrict__ y,
                                  const int* __restrict__ b_table,
                                  float* __restrict__ out)
{
    int b = blockIdx.x;
    __shared__ int ids[128];
    int t = threadIdx.x;
    if (t < 128) ids[t] = b_table[y[b] * 128 + t];
    __syncthreads();
    int c = t;
    bool on = false;
#pragma unroll 16
    for (int j = 0; j < 128; j++) on |= (ids[j] == c);
    float m = on ? 1.f : 0.f;
    const float* p = h + ((size_t)(b * 512 + c) * 16);
#pragma unroll
    for (int py = 0; py < 2; py++)
#pragma unroll
        for (int px = 0; px < 2; px++) {
            const float* q = p + (2 * py) * 4 + 2 * px;
            float v = fmaxf(fmaxf(q[0], q[1]), fmaxf(q[4], q[5]));
            out[(size_t)b * 2048 + c * 4 + py * 2 + px] = v * m;
        }
}

// ---------------------------------------------------------------------------
// FC: C[64,N] = relu?(A[64,K] @ W[N,K]^T + bias). Tiles 64x64, BK=16.
// ---------------------------------------------------------------------------
template <int K, bool RELU>
__global__ void __launch_bounds__(256)
fc64(const float* __restrict__ A, const float* __restrict__ W,
     const float* __restrict__ bias, float* __restrict__ C, int N)
{
    __shared__ float sA[16][65];
    __shared__ float sB[16][65];
    int n0 = blockIdx.x * 64;
    int tid = threadIdx.x;
    int tm = (tid / 16) * 4;
    int tn = (tid % 16) * 4;
    float acc[4][4] = {};

    for (int k0 = 0; k0 < K; k0 += 16) {
        __syncthreads();
        for (int i = tid; i < 64 * 16; i += 256) {
            int r = i / 16, kk = i % 16;
            sA[kk][r] = A[(size_t)r * K + k0 + kk];
        }
        for (int i = tid; i < 64 * 16; i += 256) {
            int cIdx = i / 16, kk = i % 16;
            int col = n0 + cIdx;
            sB[kk][cIdx] = (col < N) ? W[(size_t)col * K + k0 + kk] : 0.f;
        }
        __syncthreads();
#pragma unroll
        for (int kk = 0; kk < 16; kk++) {
            float a[4], bb[4];
#pragma unroll
            for (int i = 0; i < 4; i++) a[i] = sA[kk][tm + i];
#pragma unroll
            for (int j = 0; j < 4; j++) bb[j] = sB[kk][tn + j];
#pragma unroll
            for (int i = 0; i < 4; i++)
#pragma unroll
                for (int j = 0; j < 4; j++) acc[i][j] = fmaf(a[i], bb[j], acc[i][j]);
        }
    }
#pragma unroll
    for (int j = 0; j < 4; j++) {
        int col = n0 + tn + j;
        if (col >= N) continue;
        float bv = bias[col];
#pragma unroll
        for (int i = 0; i < 4; i++) {
            float v = acc[i][j] + bv;
            if (RELU) v = fmaxf(v, 0.f);
            C[(size_t)(tm + i) * N + col] = v;
        }
    }
}

// ---------------------------------------------------------------------------
// Launch
// ---------------------------------------------------------------------------
extern "C" void kernel_launch(void* const* d_in, const int* in_sizes, int n_in,
                              void* d_out, int out_size)
{
    const float* x    = (const float*)d_in[0];
    const int*   y    = (const int*)d_in[1];
    const int*   bt   = (const int*)d_in[2];
    const float* cw0  = (const float*)d_in[3];
    const float* cb0  = (const float*)d_in[4];
    const float* cw1  = (const float*)d_in[5];
    const float* cb1  = (const float*)d_in[6];
    const float* cw2a = (const float*)d_in[7];
    const float* cb2a = (const float*)d_in[8];
    const float* cw2b = (const float*)d_in[9];
    const float* cb2b = (const float*)d_in[10];
    const float* cw3a = (const float*)d_in[11];
    const float* cb3a = (const float*)d_in[12];
    const float* cw3b = (const float*)d_in[13];
    const float* cb3b = (const float*)d_in[14];
    const float* cw4a = (const float*)d_in[15];
    const float* cb4a = (const float*)d_in[16];
    const float* cw4b = (const float*)d_in[17];
    const float* cb4b = (const float*)d_in[18];
    const float* fw1  = (const float*)d_in[19];
    const float* fb1  = (const float*)d_in[20];
    const float* fw2  = (const float*)d_in[21];
    const float* fb2  = (const float*)d_in[22];
    const float* fw3  = (const float*)d_in[23];
    const float* fb3  = (const float*)d_in[24];

    float* A;
    float* Bp;
    cudaGetSymbolAddress((void**)&A, g_A);
    cudaGetSymbolAddress((void**)&Bp, g_B);

    // block0: conv 3->64 @64x64, relu, pool -> 32x32
    conv3x3_relu<64, 64, 3, 64, 8, 8, 2, 2, 64, 4, 3>
        <<<dim3(64, 1, 64), 256>>>(x, cw0, cb0, A);
    {
        int total = 64 * 64 * 32 * 32;
        maxpool2k<<<(total + 255) / 256, 256>>>(A, Bp, total, 64, 64, 64);
    }
    // block1: conv 64->128 @32x32, relu, pool -> 16x16
    conv3x3_relu<32, 32, 64, 128, 8, 8, 2, 2, 64, 4, 16>
        <<<dim3(16, 2, 64), 256>>>(Bp, cw1, cb1, A);
    {
        int total = 64 * 128 * 16 * 16;
        maxpool2k<<<(total + 255) / 256, 256>>>(A, Bp, total, 128, 32, 32);
    }
    // block2 @16x16: conv 128->256, relu, conv 256->256, relu, pool -> 8x8
    conv3x3_relu<16, 16, 128, 256, 8, 8, 2, 2, 64, 4, 16>
        <<<dim3(4, 4, 64), 256>>>(Bp, cw2a, cb2a, A);
    conv3x3_relu<16, 16, 256, 256, 8, 8, 2, 2, 64, 4, 16>
        <<<dim3(4, 4, 64), 256>>>(A, cw2b, cb2b, Bp);
    {
        int total = 64 * 256 * 8 * 8;
        maxpool2k<<<(total + 255) / 256, 256>>>(Bp, A, total, 256, 16, 16);
    }
    // block3 @8x8: conv 256->512, relu, conv 512->512, relu, pool -> 4x4
    conv3x3_relu<8, 8, 256, 512, 8, 8, 2, 2, 64, 4, 16>
        <<<dim3(1, 8, 64), 256>>>(A, cw3a, cb3a, Bp);
    conv3x3_relu<8, 8, 512, 512, 8, 8, 2, 2, 64, 4, 16>
        <<<dim3(1, 8, 64), 256>>>(Bp, cw3b, cb3b, A);
    {
        int total = 64 * 512 * 4 * 4;
        maxpool2k<<<(total + 255) / 256, 256>>>(A, Bp, total, 512, 8, 8);
    }
    // block4 @4x4: conv 512->512, relu, conv 512->512, relu
    conv3x3_relu<4, 4, 512, 512, 4, 4, 2, 2, 128, 4, 8>
        <<<dim3(1, 4, 64), 128>>>(Bp, cw4a, cb4a, A);
    conv3x3_relu<4, 4, 512, 512, 4, 4, 2, 2, 128, 4, 8>
        <<<dim3(1, 4, 64), 128>>>(A, cw4b, cb4b, Bp);

    // engram mask + pool -> flatten [64, 2048]
    mask_pool_flatten<<<64, 512>>>(Bp, y, bt, A);

    // classifier
    fc64<2048, true><<<64, 256>>>(A, fw1, fb1, Bp, 4096);
    fc64<4096, true><<<64, 256>>>(Bp, fw2, fb2, A, 4096);
    fc64<4096, false><<<16, 256>>>(A, fw3, fb3, (float*)d_out, 1000);
}

// round 3
// speedup vs baseline: 1.5348x; 1.5348x over previous
#include <cuda_runtime.h>
#include <cuda_bf16.h>
#include <math.h>

// ---------------------------------------------------------------------------
// Scratch (ping-pong).
// ---------------------------------------------------------------------------
__device__ float g_A[64 * 64 * 64 * 64];   // 67.1 MB
__device__ float g_B[64 * 128 * 32 * 32];  // 33.6 MB

__device__ __forceinline__ void ldrow4(float* r, const float* p) {
    float4 u = *(const float4*)p;
    float4 v = *(const float4*)(p + 4);
    r[0] = u.x; r[1] = u.y; r[2] = u.z; r[3] = u.w;
    r[4] = v.x; r[5] = v.y; r[6] = v.z; r[7] = v.w;
}
__device__ __forceinline__ void ldrow2(float* r, const float* p) {
    float2 u = *(const float2*)p;
    float2 v = *(const float2*)(p + 2);
    r[0] = u.x; r[1] = u.y; r[2] = v.x; r[3] = v.y;
}

// ---------------------------------------------------------------------------
// Direct conv3x3 SAME + bias + ReLU (+ optional fused 2x2 maxpool).
// in [B,CI,H,W], wt [CO,CI,3,3], out [B,CO,H(,/2),W(,/2)].
// NB images per block; per-thread tile RPHxRPW pixels x RC channels.
// Rolling 3-row register window; LDS.128 row/weight loads.
// ---------------------------------------------------------------------------
template <int H, int W, int CI, int CO, int NB,
          int TPH, int TPW, int RPH, int RPW,
          int OCT, int RC, int ICT, bool POOL>
__global__ void __launch_bounds__((TPH / RPH) * (TPW / RPW) * NB * (OCT / RC))
conv3x3_v2(const float* __restrict__ in, const float* __restrict__ wt,
           const float* __restrict__ bias, float* __restrict__ out)
{
    constexpr int NPXW = TPW / RPW;
    constexpr int NPXI = (TPH / RPH) * NPXW;
    constexpr int NPX  = NPXI * NB;
    constexpr int NCH  = OCT / RC;
    constexpr int NT   = NPX * NCH;
    constexpr int SP   = (RPW == 4) ? (TPW + 4) : (TPW + 2);

    __shared__ __align__(16) float s_in[NB * ICT * (TPH + 2) * SP];
    __shared__ __align__(16) float s_w[ICT * OCT * 12];

    const int tiles_w = W / TPW;
    const int ty0 = (blockIdx.x / tiles_w) * TPH;
    const int tx0 = (blockIdx.x % tiles_w) * TPW;
    const int oc0 = blockIdx.y * OCT;
    const int b0  = blockIdx.z * NB;

    const int tid = threadIdx.x;
    const int pix = tid % NPX;
    const int ch  = tid / NPX;
    const int img = pix / NPXI;
    const int p   = pix % NPXI;
    const int ly  = (p / NPXW) * RPH;
    const int lx  = (p % NPXW) * RPW;
    const int oc  = oc0 + ch * RC;

    float acc[RC][RPH][RPW];
#pragma unroll
    for (int c = 0; c < RC; c++)
#pragma unroll
        for (int yy = 0; yy < RPH; yy++)
#pragma unroll
            for (int xx = 0; xx < RPW; xx++) acc[c][yy][xx] = 0.f;

    for (int ic0 = 0; ic0 < CI; ic0 += ICT) {
        __syncthreads();
        constexpr int INEL = NB * ICT * (TPH + 2) * (TPW + 2);
        for (int idx = tid; idx < INEL; idx += NT) {
            int t = idx;
            const int ix = t % (TPW + 2); t /= (TPW + 2);
            const int iy = t % (TPH + 2); t /= (TPH + 2);
            const int ic = t % ICT;       t /= ICT;
            const int im = t;
            const int gy = ty0 + iy - 1, gx = tx0 + ix - 1;
            float v = 0.f;
            if (gy >= 0 && gy < H && gx >= 0 && gx < W)
                v = in[(((size_t)(b0 + im) * CI + ic0 + ic) * H + gy) * W + gx];
            s_in[((im * ICT + ic) * (TPH + 2) + iy) * SP + ix] = v;
        }
        constexpr int WEL = ICT * OCT * 9;
        for (int idx = tid; idx < WEL; idx += NT) {
            int t = idx;
            const int tt = t % 9;   t /= 9;
            const int ic = t % ICT; t /= ICT;
            const int o  = t;
            s_w[(ic * OCT + o) * 12 + tt] =
                wt[((size_t)(oc0 + o) * CI + ic0 + ic) * 9 + tt];
        }
        __syncthreads();

#pragma unroll 1
        for (int ic = 0; ic < ICT; ic++) {
            const float* sbase = &s_in[((img * ICT + ic) * (TPH + 2)) * SP];
            float wv[RC][9];
#pragma unroll
            for (int c = 0; c < RC; c++) {
                const float4* wp = (const float4*)&s_w[(ic * OCT + ch * RC + c) * 12];
                float4 w0 = wp[0], w1 = wp[1], w2 = wp[2];
                wv[c][0] = w0.x; wv[c][1] = w0.y; wv[c][2] = w0.z;
                wv[c][3] = w0.w; wv[c][4] = w1.x; wv[c][5] = w1.y;
                wv[c][6] = w1.z; wv[c][7] = w1.w; wv[c][8] = w2.x;
            }
            float r[3][8];
            if constexpr (RPW == 4) {
                ldrow4(r[0], sbase + (ly + 0) * SP + lx);
                ldrow4(r[1], sbase + (ly + 1) * SP + lx);
            } else {
                ldrow2(r[0], sbase + (ly + 0) * SP + lx);
                ldrow2(r[1], sbase + (ly + 1) * SP + lx);
            }
#pragma unroll
            for (int yy = 0; yy < RPH; yy++) {
                if constexpr (RPW == 4)
                    ldrow4(r[(yy + 2) % 3], sbase + (ly + yy + 2) * SP + lx);
                else
                    ldrow2(r[(yy + 2) % 3], sbase + (ly + yy + 2) * SP + lx);
                const int i0 = yy % 3, i1 = (yy + 1) % 3, i2 = (yy + 2) % 3;
#pragma unroll
                for (int c = 0; c < RC; c++)
#pragma unroll
                    for (int xx = 0; xx < RPW; xx++) {
                        float a = acc[c][yy][xx];
                        a = fmaf(wv[c][0], r[i0][xx],     a);
                        a = fmaf(wv[c][1], r[i0][xx + 1], a);
                        a = fmaf(wv[c][2], r[i0][xx + 2], a);
                        a = fmaf(wv[c][3], r[i1][xx],     a);
                        a = fmaf(wv[c][4], r[i1][xx + 1], a);
                        a = fmaf(wv[c][5], r[i1][xx + 2], a);
                        a = fmaf(wv[c][6], r[i2][xx],     a);
                        a = fmaf(wv[c][7], r[i2][xx + 1], a);
                        a = fmaf(wv[c][8], r[i2][xx + 2], a);
                        acc[c][yy][xx] = a;
                    }
            }
        }
    }

    const int bg = b0 + img;
#pragma unroll
    for (int c = 0; c < RC; c++) {
        const float bv = bias[oc + c];
        if constexpr (POOL) {
            constexpr int H2 = H / 2, W2 = W / 2;
#pragma unroll
            for (int yy2 = 0; yy2 < RPH / 2; yy2++)
#pragma unroll
                for (int xx2 = 0; xx2 < RPW / 2; xx2++) {
                    float m = fmaxf(fmaxf(acc[c][2 * yy2][2 * xx2],
                                          acc[c][2 * yy2][2 * xx2 + 1]),
                                    fmaxf(acc[c][2 * yy2 + 1][2 * xx2],
                                          acc[c][2 * yy2 + 1][2 * xx2 + 1]));
                    out[(((size_t)bg * CO + oc + c) * H2 + (ty0 + ly) / 2 + yy2) * W2
                        + (tx0 + lx) / 2 + xx2] = fmaxf(m + bv, 0.f);
                }
        } else {
#pragma unroll
            for (int yy = 0; yy < RPH; yy++)
#pragma unroll
                for (int xx = 0; xx < RPW; xx++) {
                    out[(((size_t)bg * CO + oc + c) * H + ty0 + ly + yy) * W
                        + tx0 + lx + xx] = fmaxf(acc[c][yy][xx] + bv, 0.f);
                }
        }
    }
}

// ---------------------------------------------------------------------------
// Engram mask + final 2x2 pool (4x4 -> 2x2) + flatten to [B, 2048].
// ---------------------------------------------------------------------------
__global__ void mask_pool_flatten(const float* __restrict__ h,
                                  const int* __restrict__ y,
                                  const int* __restrict__ b_table,
                                  float* __restrict__ out)
{
    int b = blockIdx.x;
    __shared__ int ids[128];
    int t = threadIdx.x;
    if (t < 128) ids[t] = b_table[y[b] * 128 + t];
    __syncthreads();
    int c = t;
    bool on = false;
#pragma unroll 16
    for (int j = 0; j < 128; j++) on |= (ids[j] == c);
    float m = on ? 1.f : 0.f;
    const float* p = h + ((size_t)(b * 512 + c) * 16);
#pragma unroll
    for (int py = 0; py < 2; py++)
#pragma unroll
        for (int px = 0; px < 2; px++) {
            const float* q = p + (2 * py) * 4 + 2 * px;
            float v = fmaxf(fmaxf(q[0], q[1]), fmaxf(q[4], q[5]));
            out[(size_t)b * 2048 + c * 4 + py * 2 + px] = v * m;
        }
}

// ---------------------------------------------------------------------------
// FC: C[64,N-tile] = relu?(A[64,K] @ W[N,K]^T + bias). 64x32 tiles, BK=16.
// grid.y = K-split (k0 = blockIdx.y*Klen, C offset blockIdx.y*64*N).
// bias==nullptr -> raw partial (no bias/relu).
// ---------------------------------------------------------------------------
template <bool RELU>
__global__ void __launch_bounds__(256)
fc_v2(const float* __restrict__ A, const float* __restrict__ W,
      const float* __restrict__ bias, float* __restrict__ C,
      int N, int K, int Klen)
{
    __shared__ __align__(16) float sA[16 * 68];
    __shared__ __align__(16) float sB[16 * 34];
    const int n0 = blockIdx.x * 32;
    const int k0base = blockIdx.y * Klen;
    float* Cp = C + (size_t)blockIdx.y * 64 * N;
    const int tid = threadIdx.x;
    const int tm = (tid / 16) * 4;
    const int tn = (tid % 16) * 2;
    float acc[4][2] = {};

    for (int k0 = k0base; k0 < k0base + Klen; k0 += 16) {
        __syncthreads();
        for (int i = tid; i < 64 * 16; i += 256) {
            int r = i / 16, kk = i % 16;
            sA[kk * 68 + r] = A[(size_t)r * K + k0 + kk];
        }
        for (int i = tid; i < 32 * 16; i += 256) {
            int cidx = i / 16, kk = i % 16;
            int col = n0 + cidx;
            sB[kk * 34 + cidx] = (col < N) ? W[(size_t)col * K + k0 + kk] : 0.f;
        }
        __syncthreads();
#pragma unroll
        for (int kk = 0; kk < 16; kk++) {
            float4 a = *(const float4*)&sA[kk * 68 + tm];
            float2 b = *(const float2*)&sB[kk * 34 + tn];
            acc[0][0] = fmaf(a.x, b.x, acc[0][0]);
            acc[0][1] = fmaf(a.x, b.y, acc[0][1]);
            acc[1][0] = fmaf(a.y, b.x, acc[1][0]);
            acc[1][1] = fmaf(a.y, b.y, acc[1][1]);
            acc[2][0] = fmaf(a.z, b.x, acc[2][0]);
            acc[2][1] = fmaf(a.z, b.y, acc[2][1]);
            acc[3][0] = fmaf(a.w, b.x, acc[3][0]);
            acc[3][1] = fmaf(a.w, b.y, acc[3][1]);
        }
    }
#pragma unroll
    for (int j = 0; j < 2; j++) {
        int col = n0 + tn + j;
        if (col >= N) continue;
        float bv = bias ? bias[col] : 0.f;
#pragma unroll
        for (int i = 0; i < 4; i++) {
            float v = acc[i][j] + bv;
            if (RELU) v = fmaxf(v, 0.f);
            Cp[(size_t)(tm + i) * N + col] = v;
        }
    }
}

__global__ void fc3_combine(const float* __restrict__ part,
                            const float* __restrict__ bias,
                            float* __restrict__ out, int N, int total)
{
    int i = blockIdx.x * blockDim.x + threadIdx.x;
    if (i >= total) return;
    int n = i % N;
    out[i] = part[i] + part[64 * N + i] + part[2 * 64 * N + i]
           + part[3 * 64 * N + i] + bias[n];
}

// ---------------------------------------------------------------------------
// Launch
// ---------------------------------------------------------------------------
extern "C" void kernel_launch(void* const* d_in, const int* in_sizes, int n_in,
                              void* d_out, int out_size)
{
    const float* x    = (const float*)d_in[0];
    const int*   y    = (const int*)d_in[1];
    const int*   bt   = (const int*)d_in[2];
    const float* cw0  = (const float*)d_in[3];
    const float* cb0  = (const float*)d_in[4];
    const float* cw1  = (const float*)d_in[5];
    const float* cb1  = (const float*)d_in[6];
    const float* cw2a = (const float*)d_in[7];
    const float* cb2a = (const float*)d_in[8];
    const float* cw2b = (const float*)d_in[9];
    const float* cb2b = (const float*)d_in[10];
    const float* cw3a = (const float*)d_in[11];
    const float* cb3a = (const float*)d_in[12];
    const float* cw3b = (const float*)d_in[13];
    const float* cb3b = (const float*)d_in[14];
    const float* cw4a = (const float*)d_in[15];
    const float* cb4a = (const float*)d_in[16];
    const float* cw4b = (const float*)d_in[17];
    const float* cb4b = (const float*)d_in[18];
    const float* fw1  = (const float*)d_in[19];
    const float* fb1  = (const float*)d_in[20];
    const float* fw2  = (const float*)d_in[21];
    const float* fb2  = (const float*)d_in[22];
    const float* fw3  = (const float*)d_in[23];
    const float* fb3  = (const float*)d_in[24];

    float* A;
    float* Bp;
    cudaGetSymbolAddress((void**)&A, g_A);
    cudaGetSymbolAddress((void**)&Bp, g_B);

    // conv0 3->64 @64x64 + pool -> A [64,64,32,32]
    conv3x3_v2<64, 64, 3, 64, 1, 16, 16, 4, 4, 64, 4, 3, true>
        <<<dim3(16, 1, 64), 256>>>(x, cw0, cb0, A);
    // conv1 64->128 @32x32 + pool -> B [64,128,16,16]
    conv3x3_v2<32, 32, 64, 128, 1, 16, 16, 4, 4, 32, 2, 16, true>
        <<<dim3(4, 4, 64), 256>>>(A, cw1, cb1, Bp);
    // conv2a 128->256 @16x16 -> A
    conv3x3_v2<16, 16, 128, 256, 1, 16, 16, 4, 4, 32, 2, 16, false>
        <<<dim3(1, 8, 64), 256>>>(Bp, cw2a, cb2a, A);
    // conv2b 256->256 @16x16 + pool -> B [64,256,8,8]
    conv3x3_v2<16, 16, 256, 256, 1, 16, 16, 4, 4, 32, 2, 16, true>
        <<<dim3(1, 8, 64), 256>>>(A, cw2b, cb2b, Bp);
    // conv3a 256->512 @8x8 -> A
    conv3x3_v2<8, 8, 256, 512, 1, 8, 8, 2, 2, 64, 4, 8, false>
        <<<dim3(1, 8, 64), 256>>>(Bp, cw3a, cb3a, A);
    // conv3b 512->512 @8x8 + pool -> B [64,512,4,4]
    conv3x3_v2<8, 8, 512, 512, 1, 8, 8, 2, 2, 64, 4, 8, true>
        <<<dim3(1, 8, 64), 256>>>(A, cw3b, cb3b, Bp);
    // conv4a 512->512 @4x4 -> A (2 images per block)
    conv3x3_v2<4, 4, 512, 512, 2, 4, 4, 2, 2, 64, 2, 8, false>
        <<<dim3(1, 8, 32), 256>>>(Bp, cw4a, cb4a, A);
    // conv4b 512->512 @4x4 -> B
    conv3x3_v2<4, 4, 512, 512, 2, 4, 4, 2, 2, 64, 2, 8, false>
        <<<dim3(1, 8, 32), 256>>>(A, cw4b, cb4b, Bp);

    // engram mask + pool -> flatten [64, 2048] -> A
    mask_pool_flatten<<<64, 512>>>(Bp, y, bt, A);

    // classifier
    fc_v2<true><<<dim3(128, 1), 256>>>(A, fw1, fb1, Bp, 4096, 2048, 2048);
    fc_v2<true><<<dim3(128, 1), 256>>>(Bp, fw2, fb2, A, 4096, 4096, 4096);
    // fc3 split-K=4 partials -> Bp, then combine
    fc_v2<false><<<dim3(32, 4), 256>>>(A, fw3, nullptr, Bp, 1000, 4096, 1024);
    fc3_combine<<<(64000 + 255) / 256, 256>>>(Bp, fb3, (float*)d_out, 1000, 64000);
}